// round 8
// baseline (speedup 1.0000x reference)
#include <cuda_runtime.h>
#include <cstdint>

// LinearPositionInterpolation — persistent segment-parallel streaming kernel.
//   index: (n,) int32 sorted keypoints (n=129, uniform spacing 32 here)
//   value: (batch, n, dim) fp32   (32, 129, 256)
//   out:   (batch, m, dim) fp32, m = index[n-1]-index[0] = 4096
//
// R7 post-mortem: four store-path variants all pin at ~22us kernel time =>
// steady-state DRAM-write floor (~134MB output/replay). Last addressable
// slack: 4096 CTAs / (148 SMs x occ 8) = 3.46 waves -> fractional wave tail.
// This version launches exactly one resident wave of persistent CTAs, each
// looping over (segment, batch) work items. Stores stay __stcs (best bench).

#define DIM    256
#define DIM4   (DIM / 4)          // 64 float4 columns per row
#define ROWS   4                  // row-groups per CTA
#define BLOCK  (ROWS * DIM4)      // 256 threads

__global__ __launch_bounds__(BLOCK)
void lpi_pers_kernel(const int* __restrict__ index,
                     const float4* __restrict__ value,
                     float4* __restrict__ out,
                     int n, int m, int nwork)
{
    const int d  = threadIdx.x & (DIM4 - 1);   // float4 column
    const int rg = threadIdx.x >> 6;           // row-group 0..ROWS-1
    const int nseg = n - 1;
    const int base = __ldg(&index[0]);

    for (int pid = blockIdx.x; pid < nwork; pid += gridDim.x) {
        const int s = pid % nseg;              // segment
        const int b = pid / nseg;              // batch

        const int x0 = __ldg(&index[s])     - base;
        const int x1 = __ldg(&index[s + 1]) - base;
        const int L  = x1 - x0;
        const float invL = 1.0f / (float)L;

        const long long vrow = ((long long)b * n + s) * DIM4 + d;
        const float4 y0 = value[vrow];
        const float4 y1 = value[vrow + DIM4];
        const float4 dy = make_float4(y1.x - y0.x, y1.y - y0.y,
                                      y1.z - y0.z, y1.w - y0.w);

        float4* orow = out + ((long long)b * m + x0 + rg) * DIM4 + d;
        const int ostep = ROWS * DIM4;

        float w = (float)(rg + 1) * invL;
        const float wstep = (float)ROWS * invL;

        if (L == 32) {
            #pragma unroll
            for (int it = 0; it < 32 / ROWS; ++it) {
                float4 o;
                o.x = fmaf(dy.x, w, y0.x);
                o.y = fmaf(dy.y, w, y0.y);
                o.z = fmaf(dy.z, w, y0.z);
                o.w = fmaf(dy.w, w, y0.w);
                __stcs(orow, o);
                orow += ostep;
                w += wstep;
            }
        } else {
            for (int p = x0 + 1 + rg; p <= x1; p += ROWS) {
                float4 o;
                o.x = fmaf(dy.x, w, y0.x);
                o.y = fmaf(dy.y, w, y0.y);
                o.z = fmaf(dy.z, w, y0.z);
                o.w = fmaf(dy.w, w, y0.w);
                __stcs(orow, o);
                orow += ostep;
                w += wstep;
            }
        }
    }
}

extern "C" void kernel_launch(void* const* d_in, const int* in_sizes, int n_in,
                              void* d_out, int out_size)
{
    const int*   index = (const int*)d_in[0];
    const float* value = (const float*)d_in[1];
    float*       outp  = (float*)d_out;

    int n = in_sizes[0];                                   // 129
    long long velems = in_sizes[1];
    int batch = (int)(velems / ((long long)n * DIM));      // 32
    int m = (int)((long long)out_size / ((long long)batch * DIM)); // 4096

    int nwork = (n - 1) * batch;                           // 4096 work items

    // One full resident wave: 148 SMs x 8 CTAs (256 thr, 30 regs -> occ 8).
    int grid = 148 * 8;
    if (grid > nwork) grid = nwork;

    lpi_pers_kernel<<<grid, BLOCK>>>(index,
                                     (const float4*)value,
                                     (float4*)outp,
                                     n, m, nwork);
}

// round 10
// speedup vs baseline: 1.1155x; 1.1155x over previous
#include <cuda_runtime.h>
#include <cstdint>

// LinearPositionInterpolation — segment-parallel, half-segment granularity.
//   index: (n,) int32 sorted keypoints (n=129, uniform spacing 32 here)
//   value: (batch, n, dim) fp32   (32, 129, 256)
//   out:   (batch, m, dim) fp32, m = index[n-1]-index[0] = 4096
//
// R8 post-mortem: persistent grid regressed (lost dense-bid write locality).
// Model: ~22us kernel = DRAM-write floor for the 134MB output stream; last
// addressable slack is the fractional wave tail (4096 CTAs / 1184 resident =
// 3.46 waves). This round: split each segment into HALVES work items ->
// 8192 CTAs -> 6.92 waves (near-integral tail), dense grid mapping kept,
// __stcs streaming stores kept, loop-incremental w kept.

#define DIM     256
#define DIM4    (DIM / 4)          // 64 float4 columns per row
#define ROWS    4                  // row-groups per CTA
#define BLOCK   (ROWS * DIM4)      // 256 threads
#define HALVES  2                  // work items per segment

__global__ __launch_bounds__(BLOCK)
void lpi_seg_kernel(const int* __restrict__ index,
                    const float4* __restrict__ value,
                    float4* __restrict__ out,
                    int n, int m)
{
    const int s  = blockIdx.x >> 1;            // segment 0..n-2
    const int h  = blockIdx.x & 1;             // half 0/1
    const int b  = blockIdx.y;                 // batch
    const int d  = threadIdx.x & (DIM4 - 1);   // float4 column
    const int rg = threadIdx.x >> 6;           // row-group 0..ROWS-1

    const int base = __ldg(&index[0]);
    const int x0   = __ldg(&index[s])     - base;
    const int x1   = __ldg(&index[s + 1]) - base;
    const int L    = x1 - x0;
    const float invL = 1.0f / (float)L;

    const long long vrow = ((long long)b * n + s) * DIM4 + d;
    const float4 y0 = value[vrow];
    const float4 y1 = value[vrow + DIM4];
    const float4 dy = make_float4(y1.x - y0.x, y1.y - y0.y,
                                  y1.z - y0.z, y1.w - y0.w);

    // This CTA covers rows [x0 + h*L/2, x0 + (h+1)*L/2) of the output
    // (positions p = x0 + h*L/2 + 1 .. x0 + (h+1)*L/2).
    const int r_lo = h * (L / 2);                       // relative row start
    const int r_hi = (h == HALVES - 1) ? L : (L / 2);   // relative row end

    float4* orow = out + ((long long)b * m + x0 + r_lo + rg) * DIM4 + d;
    const int ostep = ROWS * DIM4;

    float w = (float)(r_lo + rg + 1) * invL;
    const float wstep = (float)ROWS * invL;

    if (L == 32 && r_hi - r_lo == 16) {
        // Fast path: 16 rows, 4 iterations fully unrolled.
        #pragma unroll
        for (int it = 0; it < 16 / ROWS; ++it) {
            float4 o;
            o.x = fmaf(dy.x, w, y0.x);
            o.y = fmaf(dy.y, w, y0.y);
            o.z = fmaf(dy.z, w, y0.z);
            o.w = fmaf(dy.w, w, y0.w);
            __stcs(orow, o);
            orow += ostep;
            w += wstep;
        }
    } else {
        for (int r = r_lo + rg; r < r_hi; r += ROWS) {
            float4 o;
            o.x = fmaf(dy.x, w, y0.x);
            o.y = fmaf(dy.y, w, y0.y);
            o.z = fmaf(dy.z, w, y0.z);
            o.w = fmaf(dy.w, w, y0.w);
            __stcs(orow, o);
            orow += ostep;
            w += wstep;
        }
    }
}

extern "C" void kernel_launch(void* const* d_in, const int* in_sizes, int n_in,
                              void* d_out, int out_size)
{
    const int*   index = (const int*)d_in[0];
    const float* value = (const float*)d_in[1];
    float*       outp  = (float*)d_out;

    int n = in_sizes[0];                                   // 129
    long long velems = in_sizes[1];
    int batch = (int)(velems / ((long long)n * DIM));      // 32
    int m = (int)((long long)out_size / ((long long)batch * DIM)); // 4096

    dim3 grid((n - 1) * HALVES, batch);    // (256, 32) = 8192 CTAs
    dim3 block(BLOCK);                     // 256 threads

    lpi_seg_kernel<<<grid, block>>>(index,
                                    (const float4*)value,
                                    (float4*)outp,
                                    n, m);
}